// round 10
// baseline (speedup 1.0000x reference)
#include <cuda_runtime.h>
#include <cuda_fp16.h>
#include <cstdint>

// ---------------- problem constants ----------------
#define CCH   512
#define NB    16
#define HW    64
#define NPIX  4096
#define KTAP  9
#define STYLE_SCALE 0.04419417382415922f   // 1/sqrt(512)
#define CONV_SCALE  0.014731391274719742f  // 1/sqrt(512*9)
#define EPSV  1e-6f

// ---------------- device scratch ----------------
__device__ float  g_s[NB * CCH];                       // style * CONV_SCALE
__device__ float  g_sigma[NB * CCH];
__device__ float  g_cwt[KTAP * CCH * CCH];             // [t][ic][oc]
__device__ float  g_q2[CCH * CCH];                     // [oc][ic] = sum_t cw^2
// weights (NO sigma; sigma applied in conv epilogue):
// [b][nt=4][kc=8][t=9][ic 64][oc 128 + 8 pad]; 3 taps contiguous = 52224B bulk
__device__ __half g_wmodP[(size_t)NB * 4 * 8 * KTAP * 64 * 136];
// activations: [b][kc=8][y 66][x 66][64 ic + 8 pad]
__device__ __half g_xp2[(size_t)NB * 8 * 66 * 66 * 72];

// ---------------- prep 1: style matvec || cwt transpose + q2[oc][ic] ----------------
__global__ void k_prep(const float* __restrict__ cw, const float* __restrict__ w,
                       const float* __restrict__ sw, const float* __restrict__ sb) {
    __shared__ float sh[KTAP * 32 * 33];
    int bx = blockIdx.x, tid = threadIdx.x;
    if (bx < 256) {
        float (*tl)[32][33] = (float (*)[32][33])sh;
        int ic0 = (bx & 15) * 32, oc0 = (bx >> 4) * 32;
        int tx = tid & 31, ty = tid >> 5;
#pragma unroll
        for (int r = 0; r < 4; r++) {
            int ocl = ty + 8 * r;
            const float* src = cw + ((size_t)(oc0 + ocl) * CCH + ic0 + tx) * KTAP;
#pragma unroll
            for (int t = 0; t < KTAP; t++) tl[t][ocl][tx] = src[t];
        }
        __syncthreads();
#pragma unroll
        for (int t = 0; t < KTAP; t++)
#pragma unroll
            for (int r = 0; r < 4; r++) {
                int icl = ty + 8 * r;
                g_cwt[((size_t)t * CCH + ic0 + icl) * CCH + oc0 + tx] = tl[t][tx][icl];
            }
#pragma unroll
        for (int r = 0; r < 4; r++) {
            int ocl = ty + 8 * r;
            float a = 0.f;
#pragma unroll
            for (int t = 0; t < KTAP; t++) {
                float v = tl[t][ocl][tx];
                a += v * v;
            }
            g_q2[(size_t)(oc0 + ocl) * CCH + ic0 + tx] = a;
        }
    } else {
        int s = bx - 256;
        int base = s * 32;
        int b = base >> 9;
        float* wb = sh;
        wb[tid] = w[b * CCH + tid];
        wb[tid + 256] = w[b * CCH + tid + 256];
        __syncthreads();
        int lane = tid & 31, wid = tid >> 5;
#pragma unroll
        for (int r = 0; r < 4; r++) {
            int i = (base & 511) + wid * 4 + r;
            const float* row = sw + (size_t)i * CCH;
            float acc = 0.f;
#pragma unroll 4
            for (int j = lane; j < CCH; j += 32) acc += row[j] * wb[j];
#pragma unroll
            for (int o = 16; o; o >>= 1) acc += __shfl_xor_sync(0xFFFFFFFFu, acc, o);
            if (lane == 0) g_s[b * CCH + i] = (acc * STYLE_SCALE + sb[i]) * CONV_SCALE;
        }
    }
}

// ---------------- prep 2 (merged): xpose (blocks < 8448) || wmod-no-sigma (rest) ----------------
// xpose: one (b,kc,y) row per block, 128 threads.
// wmod: block (bp, ic) handles batches bp and bp+8, 128 threads x 4 oc each.
__global__ void k_mega(const float* __restrict__ x) {
    __shared__ float tile[64][65];
    __shared__ __half rowh[66 * 72];
    int bx = blockIdx.x, tid = threadIdx.x;
    if (bx < 8448) {
        const int ROWH = 66 * 72;
        int y = bx % 66, r = bx / 66;
        int kc = r & 7, b = r >> 3;
        __half* dstrow = g_xp2 + ((size_t)(b * 8 + kc) * 66 + y) * ROWH;
        for (int i = tid; i < ROWH / 8; i += 128)
            ((uint4*)rowh)[i] = make_uint4(0, 0, 0, 0);
        if (y > 0 && y < 65) {
            int h = y - 1;
            const float* xsrc = x + (size_t)(b * CCH + kc * 64) * NPIX + (size_t)h * HW;
            for (int e = tid; e < 64 * 64; e += 128) {
                int icl = e >> 6, wx = e & 63;
                tile[icl][wx] = xsrc[(size_t)icl * NPIX + wx];
            }
            __syncthreads();
            for (int e = tid; e < 64 * 32; e += 128) {
                int wx = e >> 5, pr = e & 31;
                *(__half2*)(rowh + (wx + 1) * 72 + pr * 2) =
                    __floats2half2_rn(tile[pr * 2][wx], tile[pr * 2 + 1][wx]);
            }
        }
        __syncthreads();
        for (int i = tid; i < ROWH / 8; i += 128)
            ((uint4*)dstrow)[i] = ((const uint4*)rowh)[i];
    } else {
        int wm = bx - 8448;
        int bp = wm >> 9, ic = wm & 511;        // bp in 0..7 -> batches bp, bp+8
        int kc = ic >> 6, icl = ic & 63;
        int oc0 = tid * 4;
        int ntt = oc0 >> 7, ocl = oc0 & 127;
        float s0v = g_s[bp * CCH + ic];
        float s1v = g_s[(bp + 8) * CCH + ic];
        const float* csrc = g_cwt + (size_t)ic * CCH + oc0;
        __half* base0 = g_wmodP +
            ((((size_t)(bp * 4 + ntt) * 8 + kc) * KTAP) * 64 + icl) * 136 + ocl;
        __half* base1 = g_wmodP +
            ((((size_t)((bp + 8) * 4 + ntt) * 8 + kc) * KTAP) * 64 + icl) * 136 + ocl;
#pragma unroll
        for (int t = 0; t < KTAP; t++) {
            float4 c = *(const float4*)(csrc + (size_t)t * CCH * CCH);
            __half2 a0 = __floats2half2_rn(c.x * s0v, c.y * s0v);
            __half2 a1 = __floats2half2_rn(c.z * s0v, c.w * s0v);
            __half2 d0 = __floats2half2_rn(c.x * s1v, c.y * s1v);
            __half2 d1 = __floats2half2_rn(c.z * s1v, c.w * s1v);
            uint2 u0 = make_uint2(*(uint32_t*)&a0, *(uint32_t*)&a1);
            uint2 u1 = make_uint2(*(uint32_t*)&d0, *(uint32_t*)&d1);
            *(uint2*)(base0 + (size_t)t * (64 * 136)) = u0;
            *(uint2*)(base1 + (size_t)t * (64 * 136)) = u1;
        }
    }
}

// ---------------- prep 3: sigma, one warp per (b, oc) ----------------
__global__ void k_sigma() {
    int gw = blockIdx.x * 8 + (threadIdx.x >> 5);
    int lane = threadIdx.x & 31;
    int b = gw >> 9, oc = gw & 511;
    const float* q = g_q2 + (size_t)oc * CCH;
    const float* s = g_s + b * CCH;
    float a = 0.f;
#pragma unroll 4
    for (int j = lane; j < CCH; j += 32) {
        float sv = s[j];
        a += sv * sv * q[j];
    }
#pragma unroll
    for (int o = 16; o; o >>= 1) a += __shfl_xor_sync(0xFFFFFFFFu, a, o);
    if (lane == 0) g_sigma[b * CCH + oc] = rsqrtf(a + EPSV);
}

// ---------------- mbarrier / bulk-copy / mma helpers ----------------
#define MBAR_INIT(addr, cnt) \
    asm volatile("mbarrier.init.shared.b64 [%0], %1;" :: "r"(addr), "r"(cnt) : "memory")
#define MBAR_EXPECT_TX(addr, bytes) \
    asm volatile("mbarrier.arrive.expect_tx.shared.b64 _, [%0], %1;" :: "r"(addr), "r"(bytes) : "memory")
#define MBAR_ARRIVE(addr) \
    asm volatile("mbarrier.arrive.shared.b64 _, [%0];" :: "r"(addr) : "memory")
#define MBAR_WAIT(addr, ph) do {                                              \
    asm volatile(                                                             \
        "{\n\t.reg .pred P1;\n\t"                                             \
        "WL_%=:\n\t"                                                          \
        "mbarrier.try_wait.parity.acquire.cta.shared::cta.b64 P1, [%0], %1, 0x989680;\n\t" \
        "@P1 bra.uni WD_%=;\n\t"                                              \
        "bra.uni WL_%=;\n\t"                                                  \
        "WD_%=:\n\t}"                                                         \
        :: "r"(addr), "r"(ph) : "memory");                                    \
} while (0)
#define MBAR_WAIT_RLX(addr, ph) do {                                          \
    asm volatile(                                                             \
        "{\n\t.reg .pred P1;\n\t"                                             \
        "WL_%=:\n\t"                                                          \
        "mbarrier.try_wait.parity.relaxed.cta.shared::cta.b64 P1, [%0], %1, 0x989680;\n\t" \
        "@P1 bra.uni WD_%=;\n\t"                                              \
        "bra.uni WL_%=;\n\t"                                                  \
        "WD_%=:\n\t}"                                                         \
        :: "r"(addr), "r"(ph) : "memory");                                    \
} while (0)
#define BULK_G2S(dst, src, bytes, mbar)                                       \
    asm volatile("cp.async.bulk.shared::cluster.global.mbarrier::complete_tx::bytes " \
                 "[%0], [%1], %2, [%3];"                                      \
                 :: "r"(dst), "l"(src), "r"(bytes), "r"(mbar) : "memory")

__device__ __forceinline__ void mma16816(float* c, const uint32_t* a, uint32_t b0, uint32_t b1) {
    asm volatile(
        "mma.sync.aligned.m16n8k16.row.col.f32.f16.f16.f32 "
        "{%0,%1,%2,%3}, {%4,%5,%6,%7}, {%8,%9}, {%0,%1,%2,%3};\n"
        : "+f"(c[0]), "+f"(c[1]), "+f"(c[2]), "+f"(c[3])
        : "r"(a[0]), "r"(a[1]), "r"(a[2]), "r"(a[3]), "r"(b0), "r"(b1));
}
__device__ __forceinline__ void ldsm_x4(uint32_t* r, uint32_t addr) {
    asm volatile("ldmatrix.sync.aligned.m8n8.x4.shared.b16 {%0,%1,%2,%3}, [%4];\n"
                 : "=r"(r[0]), "=r"(r[1]), "=r"(r[2]), "=r"(r[3]) : "r"(addr));
}
__device__ __forceinline__ void ldsm_x4_t(uint32_t* r, uint32_t addr) {
    asm volatile("ldmatrix.sync.aligned.m8n8.x4.trans.shared.b16 {%0,%1,%2,%3}, [%4];\n"
                 : "=r"(r[0]), "=r"(r[1]), "=r"(r[2]), "=r"(r[3]) : "r"(addr));
}

// ---------------- main conv kernel ----------------
// CTA: M=256 px (4 rows), N=128 oc. 512 threads, 4m x 4n warps, f32-acc MMA.
// X: 2-stage ring (one bulk per kc). B: 3-tap stages (52224B), ring-2.
// Epilogue applies sigma (post-scale), noise, bias, leaky relu from smem.
#define XBYTES 57024u
#define BBYTES 17408u
#define BSTG   52224u
#define DATA0  3072u
#define XOFF(i)  (DATA0 + (i) * XBYTES)
#define BOFF(i)  (DATA0 + 2u * XBYTES + (i) * BSTG)
#define SMEM_NEED (3072 + 2 * 57024 + 2 * 52224)   // 221568

__global__ void __launch_bounds__(512, 1)
k_conv(const float* __restrict__ noise, const float* __restrict__ nzw,
       const float* __restrict__ bias, float* __restrict__ out) {
    extern __shared__ char smem_raw[];
    const uint32_t sb = ((uint32_t)__cvta_generic_to_shared(smem_raw) + 1023u) & ~1023u;
#define FBF(s) (sb + (uint32_t)(s) * 8u)
#define FBE(s) (sb + 32u + (uint32_t)(s) * 8u)
#define FXF(s) (sb + 64u + (uint32_t)(s) * 8u)
#define FXE(s) (sb + 96u + (uint32_t)(s) * 8u)

    const int nt = blockIdx.x, mt = blockIdx.y, b = blockIdx.z;
    const int tid = threadIdx.x, lane = tid & 31, wid = tid >> 5;
    const int warp_m = wid & 3;      // output row within tile
    const int warp_n = wid >> 2;     // 32-oc slab
    const int y0 = mt * 4;

    // epilogue constants region: sigma[128] | nzw[128] | bias[128] | noise[256]
    float* fsm = (float*)__cvta_shared_to_generic(sb + 128u);

    const __half* xsrc_b = g_xp2 + ((size_t)b * 8 * 66 + y0) * (66 * 72);
    const __half* bsrc_b = g_wmodP + (size_t)(b * 4 + nt) * 8 * KTAP * 64 * 136;

    if (tid < 128) fsm[tid] = g_sigma[b * CCH + nt * 128 + tid];
    else if (tid < 256) fsm[tid] = nzw[nt * 128 + (tid - 128)];
    else if (tid < 384) fsm[tid] = bias[nt * 128 + (tid - 256)];
    else {
        int e = (tid - 384) * 2;
        const float* nr = noise + (size_t)b * NPIX + (size_t)(y0 + (e >> 6)) * HW + (e & 63);
        fsm[384 + e] = nr[0];
        fsm[384 + e + 1] = nr[1];
    }

    if (tid == 0) {
#pragma unroll
        for (int s = 0; s < 2; s++) {
            MBAR_INIT(FBF(s), 1); MBAR_INIT(FBE(s), 16);
            MBAR_INIT(FXF(s), 1); MBAR_INIT(FXE(s), 16);
        }
    }
    __syncthreads();

    if (tid == 0) {
        MBAR_EXPECT_TX(FXF(0), XBYTES);
        BULK_G2S(sb + XOFF(0), xsrc_b, XBYTES, FXF(0));
#pragma unroll
        for (int j = 0; j < 2; j++) {
            MBAR_EXPECT_TX(FBF(j), BSTG);
            BULK_G2S(sb + BOFF(j), bsrc_b + (size_t)j * 3 * (64 * 136), BSTG, FBF(j));
        }
    }

    float acc[4][4][4];
#pragma unroll
    for (int i = 0; i < 4; i++)
#pragma unroll
        for (int j = 0; j < 4; j++)
#pragma unroll
            for (int k = 0; k < 4; k++) acc[i][j][k] = 0.f;

    const int off_m = ((lane >> 3) & 1) * 8 + (lane & 7);
    const int off_k2 = ((lane >> 4) * 8) * 2;
    const uint32_t b_lane_off = (uint32_t)((lane & 15) * 272 +
                                           (warp_n * 32 + (lane >> 4) * 8) * 2);

    int ist = 0;
    for (int kc = 0; kc < 8; kc++) {
        MBAR_WAIT(FXF(kc & 1), (kc >> 1) & 1);
        for (int sidx = 0; sidx < 3; sidx++, ist++) {
            const int slot = ist & 1, ph = (ist >> 1) & 1;
            MBAR_WAIT(FBF(slot), ph);

            const uint32_t Arow = sb + XOFF(kc & 1) +
                (uint32_t)(((warp_m + sidx) * 66 + off_m) * 144) + off_k2;
            const uint32_t Bst = sb + BOFF(slot) + b_lane_off;

#pragma unroll
            for (int tp = 0; tp < 3; tp++) {
                const uint32_t A0 = Arow + (uint32_t)(tp * 144);
                const uint32_t Bb = Bst + (uint32_t)tp * BBYTES;
#pragma unroll
                for (int k16 = 0; k16 < 4; k16++) {
                    uint32_t a[4][4];
#pragma unroll
                    for (int mf = 0; mf < 4; mf++)
                        ldsm_x4(a[mf], A0 + mf * 2304 + k16 * 32);
#pragma unroll
                    for (int g = 0; g < 2; g++) {
                        uint32_t bf[4];
                        ldsm_x4_t(bf, Bb + k16 * (16 * 272) + g * 32);
#pragma unroll
                        for (int mf = 0; mf < 4; mf++) {
                            mma16816(acc[mf][g * 2],     a[mf], bf[0], bf[1]);
                            mma16816(acc[mf][g * 2 + 1], a[mf], bf[2], bf[3]);
                        }
                    }
                }
            }

            if (lane == 0) {
                MBAR_ARRIVE(FBE(slot));
                if (sidx == 2) MBAR_ARRIVE(FXE(kc & 1));
                if (wid == (ist & 15)) {           // rotating producer duty
                    int j = ist + 2;
                    if (j < 24) {
                        int js = j & 1;
                        MBAR_WAIT_RLX(FBE(js), ((j >> 1) + 1) & 1);
                        int jkc = j / 3, jsx = j - jkc * 3;
                        MBAR_EXPECT_TX(FBF(js), BSTG);
                        BULK_G2S(sb + BOFF(js),
                                 bsrc_b + (size_t)(jkc * KTAP + jsx * 3) * (64 * 136),
                                 BSTG, FBF(js));
                    }
                    if (sidx == 0 && kc < 7) {
                        int s2 = (kc + 1) & 1;
                        MBAR_WAIT_RLX(FXE(s2), (((kc + 1) >> 1) + 1) & 1);
                        MBAR_EXPECT_TX(FXF(s2), XBYTES);
                        BULK_G2S(sb + XOFF(s2),
                                 xsrc_b + (size_t)(kc + 1) * 66 * (66 * 72),
                                 XBYTES, FXF(s2));
                    }
                }
            }
        }
    }

    // -------- epilogue: sigma post-scale + noise + bias + leaky relu --------
    const int g = lane >> 2, tq = lane & 3;
    const int yrow = y0 + warp_m;
    float nzv[4][2];
#pragma unroll
    for (int mf = 0; mf < 4; mf++) {
        nzv[mf][0] = fsm[384 + warp_m * 64 + mf * 16 + g];
        nzv[mf][1] = fsm[384 + warp_m * 64 + mf * 16 + g + 8];
    }
    const size_t outb = (size_t)b * CCH * NPIX;
#pragma unroll
    for (int nf = 0; nf < 4; nf++) {
        int ocl = warp_n * 32 + nf * 8 + tq * 2;
        float sg0 = fsm[ocl], sg1 = fsm[ocl + 1];
        float nw0 = fsm[128 + ocl], nw1 = fsm[128 + ocl + 1];
        float bi0 = fsm[256 + ocl], bi1 = fsm[256 + ocl + 1];
        float* o0 = out + outb + (size_t)(nt * 128 + ocl) * NPIX + (size_t)yrow * HW;
#pragma unroll
        for (int mf = 0; mf < 4; mf++) {
            int x0 = mf * 16 + g;
            float v;
            v = acc[mf][nf][0] * sg0 + nw0 * nzv[mf][0] + bi0; o0[x0]            = v > 0.f ? v : 0.2f * v;
            v = acc[mf][nf][1] * sg1 + nw1 * nzv[mf][0] + bi1; o0[NPIX + x0]     = v > 0.f ? v : 0.2f * v;
            v = acc[mf][nf][2] * sg0 + nw0 * nzv[mf][1] + bi0; o0[x0 + 8]        = v > 0.f ? v : 0.2f * v;
            v = acc[mf][nf][3] * sg1 + nw1 * nzv[mf][1] + bi1; o0[NPIX + x0 + 8] = v > 0.f ? v : 0.2f * v;
        }
    }
}

// ---------------- launcher (4 launches; k_conv is 4th -> profiled) ----------------
extern "C" void kernel_launch(void* const* d_in, const int* in_sizes, int n_in,
                              void* d_out, int out_size) {
    const float* x     = (const float*)d_in[0];
    const float* w     = (const float*)d_in[1];
    const float* sw    = (const float*)d_in[2];
    const float* sb    = (const float*)d_in[3];
    const float* cw    = (const float*)d_in[4];
    const float* nzw   = (const float*)d_in[5];
    const float* bias  = (const float*)d_in[6];
    const float* noise = (const float*)d_in[7];
    float* out = (float*)d_out;

    cudaFuncSetAttribute((const void*)k_conv,
                         cudaFuncAttributeMaxDynamicSharedMemorySize, SMEM_NEED);

    k_prep<<<512, 256>>>(cw, w, sw, sb);
    k_mega<<<8448 + 4096, 128>>>(x);
    k_sigma<<<NB * CCH / 8, 256>>>();
    k_conv<<<dim3(4, 16, NB), 512, SMEM_NEED>>>(noise, nzw, bias, out);
}

// round 11
// speedup vs baseline: 1.0130x; 1.0130x over previous
#include <cuda_runtime.h>
#include <cuda_fp16.h>
#include <cstdint>

// ---------------- problem constants ----------------
#define CCH   512
#define NB    16
#define HW    64
#define NPIX  4096
#define KTAP  9
#define STYLE_SCALE 0.04419417382415922f   // 1/sqrt(512)
#define CONV_SCALE  0.014731391274719742f  // 1/sqrt(512*9)
#define EPSV  1e-6f

// ---------------- device scratch ----------------
__device__ float  g_s[NB * CCH];                       // style * CONV_SCALE
__device__ float  g_sigma[NB * CCH];
__device__ float  g_cwt[KTAP * CCH * CCH];             // [t][ic][oc]
__device__ float  g_q2[CCH * CCH];                     // [oc][ic] = sum_t cw^2
// weights (NO sigma; sigma applied in conv epilogue):
// [b][nt=4][kc=8][t=9][ic 64][oc 128 + 8 pad]; 3 taps contiguous = 52224B bulk
__device__ __half g_wmodP[(size_t)NB * 4 * 8 * KTAP * 64 * 136];
// activations: [b][kc=8][y 66][x 66][64 ic + 8 pad]
__device__ __half g_xp2[(size_t)NB * 8 * 66 * 66 * 72];

// ---------------- prep launch 1: xpose || cwt+q2 || style (all independent) ----------------
// blocks [0,8448): xpose, one (b,kc,y) row each
// blocks [8448,8704): cwt transpose + q2, one 32x32 (ic,oc) tile each
// blocks [8704,10752): style, 4 warps = 4 outputs each
__global__ void k_p1(const float* __restrict__ x, const float* __restrict__ cw,
                     const float* __restrict__ w, const float* __restrict__ sw,
                     const float* __restrict__ sb) {
    __shared__ float sh[KTAP * 32 * 33];               // 38016B, unioned
    int bx = blockIdx.x, tid = threadIdx.x;
    if (bx < 8448) {
        const int ROWH = 66 * 72;
        float (*tile)[65] = (float (*)[65])sh;                  // 16640B
        __half* rowh = (__half*)(sh + 4160);                    // 9504B
        int y = bx % 66, r = bx / 66;
        int kc = r & 7, b = r >> 3;
        __half* dstrow = g_xp2 + ((size_t)(b * 8 + kc) * 66 + y) * ROWH;
        for (int i = tid; i < ROWH / 8; i += 128)
            ((uint4*)rowh)[i] = make_uint4(0, 0, 0, 0);
        if (y > 0 && y < 65) {
            int h = y - 1;
            const float* xsrc = x + (size_t)(b * CCH + kc * 64) * NPIX + (size_t)h * HW;
            for (int e = tid; e < 64 * 64; e += 128) {
                int icl = e >> 6, wx = e & 63;
                tile[icl][wx] = xsrc[(size_t)icl * NPIX + wx];
            }
            __syncthreads();
            for (int e = tid; e < 64 * 32; e += 128) {
                int wx = e >> 5, pr = e & 31;
                *(__half2*)(rowh + (wx + 1) * 72 + pr * 2) =
                    __floats2half2_rn(tile[pr * 2][wx], tile[pr * 2 + 1][wx]);
            }
        }
        __syncthreads();
        for (int i = tid; i < ROWH / 8; i += 128)
            ((uint4*)dstrow)[i] = ((const uint4*)rowh)[i];
    } else if (bx < 8704) {
        float (*tl)[32][33] = (float (*)[32][33])sh;
        int t32 = bx - 8448;
        int ic0 = (t32 & 15) * 32, oc0 = (t32 >> 4) * 32;
        int tx = tid & 31, ty = tid >> 5;                       // ty in 0..3
#pragma unroll
        for (int r = 0; r < 8; r++) {
            int ocl = r * 4 + ty;
            const float* src = cw + ((size_t)(oc0 + ocl) * CCH + ic0 + tx) * KTAP;
#pragma unroll
            for (int t = 0; t < KTAP; t++) tl[t][ocl][tx] = src[t];
        }
        __syncthreads();
#pragma unroll
        for (int t = 0; t < KTAP; t++)
#pragma unroll
            for (int r = 0; r < 8; r++) {
                int icl = r * 4 + ty;
                g_cwt[((size_t)t * CCH + ic0 + icl) * CCH + oc0 + tx] = tl[t][tx][icl];
            }
#pragma unroll
        for (int r = 0; r < 8; r++) {
            int ocl = r * 4 + ty;
            float a = 0.f;
#pragma unroll
            for (int t = 0; t < KTAP; t++) {
                float v = tl[t][ocl][tx];
                a += v * v;
            }
            g_q2[(size_t)(oc0 + ocl) * CCH + ic0 + tx] = a;
        }
    } else {
        int gw = (bx - 8704) * 4 + (tid >> 5);                  // 0..8191
        int lane = tid & 31;
        int b = gw >> 9, i = gw & 511;
        const float* row = sw + (size_t)i * CCH;
        const float* wb = w + b * CCH;
        float acc = 0.f;
#pragma unroll 4
        for (int j = lane; j < CCH; j += 32) acc += row[j] * wb[j];
#pragma unroll
        for (int o = 16; o; o >>= 1) acc += __shfl_xor_sync(0xFFFFFFFFu, acc, o);
        if (lane == 0) g_s[b * CCH + i] = (acc * STYLE_SCALE + sb[i]) * CONV_SCALE;
    }
}

// ---------------- prep launch 2: wmod (no sigma) || sigma ----------------
// blocks [0,4096): wmod, block (bp,ic) handles batches bp and bp+8
// blocks [4096,6144): sigma, 4 warps = 4 (b,oc) outputs each
__global__ void k_p2() {
    int bx = blockIdx.x, tid = threadIdx.x;
    if (bx < 4096) {
        int bp = bx >> 9, ic = bx & 511;
        int kc = ic >> 6, icl = ic & 63;
        int oc0 = tid * 4;
        int ntt = oc0 >> 7, ocl = oc0 & 127;
        float s0v = g_s[bp * CCH + ic];
        float s1v = g_s[(bp + 8) * CCH + ic];
        const float* csrc = g_cwt + (size_t)ic * CCH + oc0;
        __half* base0 = g_wmodP +
            ((((size_t)(bp * 4 + ntt) * 8 + kc) * KTAP) * 64 + icl) * 136 + ocl;
        __half* base1 = g_wmodP +
            ((((size_t)((bp + 8) * 4 + ntt) * 8 + kc) * KTAP) * 64 + icl) * 136 + ocl;
#pragma unroll
        for (int t = 0; t < KTAP; t++) {
            float4 c = *(const float4*)(csrc + (size_t)t * CCH * CCH);
            __half2 a0 = __floats2half2_rn(c.x * s0v, c.y * s0v);
            __half2 a1 = __floats2half2_rn(c.z * s0v, c.w * s0v);
            __half2 d0 = __floats2half2_rn(c.x * s1v, c.y * s1v);
            __half2 d1 = __floats2half2_rn(c.z * s1v, c.w * s1v);
            uint2 u0 = make_uint2(*(uint32_t*)&a0, *(uint32_t*)&a1);
            uint2 u1 = make_uint2(*(uint32_t*)&d0, *(uint32_t*)&d1);
            *(uint2*)(base0 + (size_t)t * (64 * 136)) = u0;
            *(uint2*)(base1 + (size_t)t * (64 * 136)) = u1;
        }
    } else {
        int gw = (bx - 4096) * 4 + (tid >> 5);
        int lane = tid & 31;
        int b = gw >> 9, oc = gw & 511;
        const float* q = g_q2 + (size_t)oc * CCH;
        const float* s = g_s + b * CCH;
        float a = 0.f;
#pragma unroll 4
        for (int j = lane; j < CCH; j += 32) {
            float sv = s[j];
            a += sv * sv * q[j];
        }
#pragma unroll
        for (int o = 16; o; o >>= 1) a += __shfl_xor_sync(0xFFFFFFFFu, a, o);
        if (lane == 0) g_sigma[b * CCH + oc] = rsqrtf(a + EPSV);
    }
}

// ---------------- mbarrier / bulk-copy / mma helpers ----------------
#define MBAR_INIT(addr, cnt) \
    asm volatile("mbarrier.init.shared.b64 [%0], %1;" :: "r"(addr), "r"(cnt) : "memory")
#define MBAR_EXPECT_TX(addr, bytes) \
    asm volatile("mbarrier.arrive.expect_tx.shared.b64 _, [%0], %1;" :: "r"(addr), "r"(bytes) : "memory")
#define MBAR_ARRIVE(addr) \
    asm volatile("mbarrier.arrive.shared.b64 _, [%0];" :: "r"(addr) : "memory")
#define MBAR_WAIT(addr, ph) do {                                              \
    asm volatile(                                                             \
        "{\n\t.reg .pred P1;\n\t"                                             \
        "WL_%=:\n\t"                                                          \
        "mbarrier.try_wait.parity.acquire.cta.shared::cta.b64 P1, [%0], %1, 0x989680;\n\t" \
        "@P1 bra.uni WD_%=;\n\t"                                              \
        "bra.uni WL_%=;\n\t"                                                  \
        "WD_%=:\n\t}"                                                         \
        :: "r"(addr), "r"(ph) : "memory");                                    \
} while (0)
#define MBAR_WAIT_RLX(addr, ph) do {                                          \
    asm volatile(                                                             \
        "{\n\t.reg .pred P1;\n\t"                                             \
        "WL_%=:\n\t"                                                          \
        "mbarrier.try_wait.parity.relaxed.cta.shared::cta.b64 P1, [%0], %1, 0x989680;\n\t" \
        "@P1 bra.uni WD_%=;\n\t"                                              \
        "bra.uni WL_%=;\n\t"                                                  \
        "WD_%=:\n\t}"                                                         \
        :: "r"(addr), "r"(ph) : "memory");                                    \
} while (0)
#define BULK_G2S(dst, src, bytes, mbar)                                       \
    asm volatile("cp.async.bulk.shared::cluster.global.mbarrier::complete_tx::bytes " \
                 "[%0], [%1], %2, [%3];"                                      \
                 :: "r"(dst), "l"(src), "r"(bytes), "r"(mbar) : "memory")

__device__ __forceinline__ void mma16816(float* c, const uint32_t* a, uint32_t b0, uint32_t b1) {
    asm volatile(
        "mma.sync.aligned.m16n8k16.row.col.f32.f16.f16.f32 "
        "{%0,%1,%2,%3}, {%4,%5,%6,%7}, {%8,%9}, {%0,%1,%2,%3};\n"
        : "+f"(c[0]), "+f"(c[1]), "+f"(c[2]), "+f"(c[3])
        : "r"(a[0]), "r"(a[1]), "r"(a[2]), "r"(a[3]), "r"(b0), "r"(b1));
}
__device__ __forceinline__ void ldsm_x4(uint32_t* r, uint32_t addr) {
    asm volatile("ldmatrix.sync.aligned.m8n8.x4.shared.b16 {%0,%1,%2,%3}, [%4];\n"
                 : "=r"(r[0]), "=r"(r[1]), "=r"(r[2]), "=r"(r[3]) : "r"(addr));
}
__device__ __forceinline__ void ldsm_x4_t(uint32_t* r, uint32_t addr) {
    asm volatile("ldmatrix.sync.aligned.m8n8.x4.trans.shared.b16 {%0,%1,%2,%3}, [%4];\n"
                 : "=r"(r[0]), "=r"(r[1]), "=r"(r[2]), "=r"(r[3]) : "r"(addr));
}

// ---------------- main conv kernel (unchanged mainloop from R10) ----------------
#define XBYTES 57024u
#define BBYTES 17408u
#define BSTG   52224u
#define DATA0  3072u
#define XOFF(i)  (DATA0 + (i) * XBYTES)
#define BOFF(i)  (DATA0 + 2u * XBYTES + (i) * BSTG)
#define SMEM_NEED (3072 + 2 * 57024 + 2 * 52224)   // 221568

__global__ void __launch_bounds__(512, 1)
k_conv(const float* __restrict__ noise, const float* __restrict__ nzw,
       const float* __restrict__ bias, float* __restrict__ out) {
    extern __shared__ char smem_raw[];
    const uint32_t sb = ((uint32_t)__cvta_generic_to_shared(smem_raw) + 1023u) & ~1023u;
#define FBF(s) (sb + (uint32_t)(s) * 8u)
#define FBE(s) (sb + 32u + (uint32_t)(s) * 8u)
#define FXF(s) (sb + 64u + (uint32_t)(s) * 8u)
#define FXE(s) (sb + 96u + (uint32_t)(s) * 8u)

    const int nt = blockIdx.x, mt = blockIdx.y, b = blockIdx.z;
    const int tid = threadIdx.x, lane = tid & 31, wid = tid >> 5;
    const int warp_m = wid & 3;
    const int warp_n = wid >> 2;
    const int y0 = mt * 4;

    float* fsm = (float*)__cvta_shared_to_generic(sb + 128u);

    const __half* xsrc_b = g_xp2 + ((size_t)b * 8 * 66 + y0) * (66 * 72);
    const __half* bsrc_b = g_wmodP + (size_t)(b * 4 + nt) * 8 * KTAP * 64 * 136;

    if (tid < 128) fsm[tid] = g_sigma[b * CCH + nt * 128 + tid];
    else if (tid < 256) fsm[tid] = nzw[nt * 128 + (tid - 128)];
    else if (tid < 384) fsm[tid] = bias[nt * 128 + (tid - 256)];
    else {
        int e = (tid - 384) * 2;
        const float* nr = noise + (size_t)b * NPIX + (size_t)(y0 + (e >> 6)) * HW + (e & 63);
        fsm[384 + e] = nr[0];
        fsm[384 + e + 1] = nr[1];
    }

    if (tid == 0) {
#pragma unroll
        for (int s = 0; s < 2; s++) {
            MBAR_INIT(FBF(s), 1); MBAR_INIT(FBE(s), 16);
            MBAR_INIT(FXF(s), 1); MBAR_INIT(FXE(s), 16);
        }
    }
    __syncthreads();

    if (tid == 0) {
        MBAR_EXPECT_TX(FXF(0), XBYTES);
        BULK_G2S(sb + XOFF(0), xsrc_b, XBYTES, FXF(0));
#pragma unroll
        for (int j = 0; j < 2; j++) {
            MBAR_EXPECT_TX(FBF(j), BSTG);
            BULK_G2S(sb + BOFF(j), bsrc_b + (size_t)j * 3 * (64 * 136), BSTG, FBF(j));
        }
    }

    float acc[4][4][4];
#pragma unroll
    for (int i = 0; i < 4; i++)
#pragma unroll
        for (int j = 0; j < 4; j++)
#pragma unroll
            for (int k = 0; k < 4; k++) acc[i][j][k] = 0.f;

    const int off_m = ((lane >> 3) & 1) * 8 + (lane & 7);
    const int off_k2 = ((lane >> 4) * 8) * 2;
    const uint32_t b_lane_off = (uint32_t)((lane & 15) * 272 +
                                           (warp_n * 32 + (lane >> 4) * 8) * 2);

    int ist = 0;
    for (int kc = 0; kc < 8; kc++) {
        MBAR_WAIT(FXF(kc & 1), (kc >> 1) & 1);
        for (int sidx = 0; sidx < 3; sidx++, ist++) {
            const int slot = ist & 1, ph = (ist >> 1) & 1;
            MBAR_WAIT(FBF(slot), ph);

            const uint32_t Arow = sb + XOFF(kc & 1) +
                (uint32_t)(((warp_m + sidx) * 66 + off_m) * 144) + off_k2;
            const uint32_t Bst = sb + BOFF(slot) + b_lane_off;

#pragma unroll
            for (int tp = 0; tp < 3; tp++) {
                const uint32_t A0 = Arow + (uint32_t)(tp * 144);
                const uint32_t Bb = Bst + (uint32_t)tp * BBYTES;
#pragma unroll
                for (int k16 = 0; k16 < 4; k16++) {
                    uint32_t a[4][4];
#pragma unroll
                    for (int mf = 0; mf < 4; mf++)
                        ldsm_x4(a[mf], A0 + mf * 2304 + k16 * 32);
#pragma unroll
                    for (int g = 0; g < 2; g++) {
                        uint32_t bf[4];
                        ldsm_x4_t(bf, Bb + k16 * (16 * 272) + g * 32);
#pragma unroll
                        for (int mf = 0; mf < 4; mf++) {
                            mma16816(acc[mf][g * 2],     a[mf], bf[0], bf[1]);
                            mma16816(acc[mf][g * 2 + 1], a[mf], bf[2], bf[3]);
                        }
                    }
                }
            }

            if (lane == 0) {
                MBAR_ARRIVE(FBE(slot));
                if (sidx == 2) MBAR_ARRIVE(FXE(kc & 1));
                if (wid == (ist & 15)) {
                    int j = ist + 2;
                    if (j < 24) {
                        int js = j & 1;
                        MBAR_WAIT_RLX(FBE(js), ((j >> 1) + 1) & 1);
                        int jkc = j / 3, jsx = j - jkc * 3;
                        MBAR_EXPECT_TX(FBF(js), BSTG);
                        BULK_G2S(sb + BOFF(js),
                                 bsrc_b + (size_t)(jkc * KTAP + jsx * 3) * (64 * 136),
                                 BSTG, FBF(js));
                    }
                    if (sidx == 0 && kc < 7) {
                        int s2 = (kc + 1) & 1;
                        MBAR_WAIT_RLX(FXE(s2), (((kc + 1) >> 1) + 1) & 1);
                        MBAR_EXPECT_TX(FXF(s2), XBYTES);
                        BULK_G2S(sb + XOFF(s2),
                                 xsrc_b + (size_t)(kc + 1) * 66 * (66 * 72),
                                 XBYTES, FXF(s2));
                    }
                }
            }
        }
    }

    // -------- epilogue: sigma post-scale + noise + bias + leaky relu --------
    const int g = lane >> 2, tq = lane & 3;
    const int yrow = y0 + warp_m;
    float nzv[4][2];
#pragma unroll
    for (int mf = 0; mf < 4; mf++) {
        nzv[mf][0] = fsm[384 + warp_m * 64 + mf * 16 + g];
        nzv[mf][1] = fsm[384 + warp_m * 64 + mf * 16 + g + 8];
    }
    const size_t outb = (size_t)b * CCH * NPIX;
#pragma unroll
    for (int nf = 0; nf < 4; nf++) {
        int ocl = warp_n * 32 + nf * 8 + tq * 2;
        float sg0 = fsm[ocl], sg1 = fsm[ocl + 1];
        float nw0 = fsm[128 + ocl], nw1 = fsm[128 + ocl + 1];
        float bi0 = fsm[256 + ocl], bi1 = fsm[256 + ocl + 1];
        float* o0 = out + outb + (size_t)(nt * 128 + ocl) * NPIX + (size_t)yrow * HW;
#pragma unroll
        for (int mf = 0; mf < 4; mf++) {
            int x0 = mf * 16 + g;
            float v;
            v = acc[mf][nf][0] * sg0 + nw0 * nzv[mf][0] + bi0; __stwt(o0 + x0,            v > 0.f ? v : 0.2f * v);
            v = acc[mf][nf][1] * sg1 + nw1 * nzv[mf][0] + bi1; __stwt(o0 + NPIX + x0,     v > 0.f ? v : 0.2f * v);
            v = acc[mf][nf][2] * sg0 + nw0 * nzv[mf][1] + bi0; __stwt(o0 + x0 + 8,        v > 0.f ? v : 0.2f * v);
            v = acc[mf][nf][3] * sg1 + nw1 * nzv[mf][1] + bi1; __stwt(o0 + NPIX + x0 + 8, v > 0.f ? v : 0.2f * v);
        }
    }
}

// ---------------- launcher (3 launches) ----------------
extern "C" void kernel_launch(void* const* d_in, const int* in_sizes, int n_in,
                              void* d_out, int out_size) {
    const float* x     = (const float*)d_in[0];
    const float* w     = (const float*)d_in[1];
    const float* sw    = (const float*)d_in[2];
    const float* sb    = (const float*)d_in[3];
    const float* cw    = (const float*)d_in[4];
    const float* nzw   = (const float*)d_in[5];
    const float* bias  = (const float*)d_in[6];
    const float* noise = (const float*)d_in[7];
    float* out = (float*)d_out;

    cudaFuncSetAttribute((const void*)k_conv,
                         cudaFuncAttributeMaxDynamicSharedMemorySize, SMEM_NEED);

    k_p1<<<8448 + 256 + 2048, 128>>>(x, cw, w, sw, sb);
    k_p2<<<4096 + 2048, 128>>>();
    k_conv<<<dim3(4, 16, NB), 512, SMEM_NEED>>>(noise, nzw, bias, out);
}

// round 12
// speedup vs baseline: 1.1076x; 1.0934x over previous
#include <cuda_runtime.h>
#include <cuda_fp16.h>
#include <cstdint>

// ---------------- problem constants ----------------
#define CCH   512
#define NB    16
#define HW    64
#define NPIX  4096
#define KTAP  9
#define NTILES 1024
#define STYLE_SCALE 0.04419417382415922f   // 1/sqrt(512)
#define CONV_SCALE  0.014731391274719742f  // 1/sqrt(512*9)
#define EPSV  1e-6f

// ---------------- device scratch ----------------
__device__ float  g_s[NB * CCH];                       // style * CONV_SCALE
__device__ float  g_sigma[NB * CCH];
__device__ float  g_cwt[KTAP * CCH * CCH];             // [t][ic][oc]
__device__ float  g_q2[CCH * CCH];                     // [oc][ic] = sum_t cw^2
// weights (NO sigma): [b][nt=4][kc=8][t=9][ic 64][oc 128+8]; 3 taps = 52224B bulk
__device__ __half g_wmodP[(size_t)NB * 4 * 8 * KTAP * 64 * 136];
// activations: [b][kc=8][y 66][x 66][64 ic + 8 pad]
__device__ __half g_xp2[(size_t)NB * 8 * 66 * 66 * 72];

// ---------------- prep launch 1: xpose || cwt+q2 || style (17.8KB smem union) ----------------
__global__ void k_p1(const float* __restrict__ x, const float* __restrict__ cw,
                     const float* __restrict__ w, const float* __restrict__ sw,
                     const float* __restrict__ sb) {
    __shared__ float sh[4456];                          // 17824 B
    int bx = blockIdx.x, tid = threadIdx.x;
    if (bx < 8448) {
        const int ROWH = 66 * 72;
        float (*tile)[65] = (float (*)[65])sh;          // 32x65 = 8320B
        __half* rowh = (__half*)(sh + 2080);            // 9504B
        int y = bx % 66, r = bx / 66;
        int kc = r & 7, b = r >> 3;
        __half* dstrow = g_xp2 + ((size_t)(b * 8 + kc) * 66 + y) * ROWH;
        for (int i = tid; i < ROWH / 8; i += 128)
            ((uint4*)rowh)[i] = make_uint4(0, 0, 0, 0);
        if (y > 0 && y < 65) {
            int h = y - 1;
#pragma unroll
            for (int p = 0; p < 2; p++) {
                __syncthreads();
                const float* xsrc = x + (size_t)(b * CCH + kc * 64 + p * 32) * NPIX
                                      + (size_t)h * HW;
                for (int e = tid; e < 32 * 64; e += 128) {
                    int icl = e >> 6, wx = e & 63;
                    tile[icl][wx] = xsrc[(size_t)icl * NPIX + wx];
                }
                __syncthreads();
                for (int e = tid; e < 64 * 16; e += 128) {
                    int wx = e >> 4, pr = e & 15;
                    *(__half2*)(rowh + (wx + 1) * 72 + p * 32 + pr * 2) =
                        __floats2half2_rn(tile[pr * 2][wx], tile[pr * 2 + 1][wx]);
                }
            }
        }
        __syncthreads();
        for (int i = tid; i < ROWH / 8; i += 128)
            ((uint4*)dstrow)[i] = ((const uint4*)rowh)[i];
    } else if (bx < 8704) {
        float (*tl)[32][33] = (float (*)[32][33])sh;    // 3x32x33 = 12672B
        int t32 = bx - 8448;
        int ic0 = (t32 & 15) * 32, oc0 = (t32 >> 4) * 32;
        int tx = tid & 31, ty = tid >> 5;               // ty 0..3
        float qacc[8] = {0, 0, 0, 0, 0, 0, 0, 0};
#pragma unroll
        for (int c = 0; c < 3; c++) {
            __syncthreads();
#pragma unroll
            for (int r = 0; r < 8; r++) {
                int ocl = r * 4 + ty;
                const float* src = cw + ((size_t)(oc0 + ocl) * CCH + ic0 + tx) * KTAP + c * 3;
#pragma unroll
                for (int t = 0; t < 3; t++) tl[t][ocl][tx] = src[t];
            }
            __syncthreads();
#pragma unroll
            for (int t = 0; t < 3; t++)
#pragma unroll
                for (int r = 0; r < 8; r++) {
                    int icl = r * 4 + ty;
                    g_cwt[((size_t)(c * 3 + t) * CCH + ic0 + icl) * CCH + oc0 + tx] =
                        tl[t][tx][icl];
                }
#pragma unroll
            for (int r = 0; r < 8; r++) {
                int ocl = r * 4 + ty;
#pragma unroll
                for (int t = 0; t < 3; t++) {
                    float v = tl[t][ocl][tx];
                    qacc[r] += v * v;
                }
            }
        }
#pragma unroll
        for (int r = 0; r < 8; r++) {
            int ocl = r * 4 + ty;
            g_q2[(size_t)(oc0 + ocl) * CCH + ic0 + tx] = qacc[r];
        }
    } else {
        int gw = (bx - 8704) * 4 + (tid >> 5);
        int lane = tid & 31;
        int b = gw >> 9, i = gw & 511;
        const float* row = sw + (size_t)i * CCH;
        const float* wb = w + b * CCH;
        float acc = 0.f;
#pragma unroll 4
        for (int j = lane; j < CCH; j += 32) acc += row[j] * wb[j];
#pragma unroll
        for (int o = 16; o; o >>= 1) acc += __shfl_xor_sync(0xFFFFFFFFu, acc, o);
        if (lane == 0) g_s[b * CCH + i] = (acc * STYLE_SCALE + sb[i]) * CONV_SCALE;
    }
}

// ---------------- prep launch 2: wmod (no sigma) || sigma ----------------
__global__ void k_p2() {
    int bx = blockIdx.x, tid = threadIdx.x;
    if (bx < 4096) {
        int bp = bx >> 9, ic = bx & 511;
        int kc = ic >> 6, icl = ic & 63;
        int oc0 = tid * 4;
        int ntt = oc0 >> 7, ocl = oc0 & 127;
        float s0v = g_s[bp * CCH + ic];
        float s1v = g_s[(bp + 8) * CCH + ic];
        const float* csrc = g_cwt + (size_t)ic * CCH + oc0;
        __half* base0 = g_wmodP +
            ((((size_t)(bp * 4 + ntt) * 8 + kc) * KTAP) * 64 + icl) * 136 + ocl;
        __half* base1 = g_wmodP +
            ((((size_t)((bp + 8) * 4 + ntt) * 8 + kc) * KTAP) * 64 + icl) * 136 + ocl;
#pragma unroll
        for (int t = 0; t < KTAP; t++) {
            float4 c = *(const float4*)(csrc + (size_t)t * CCH * CCH);
            __half2 a0 = __floats2half2_rn(c.x * s0v, c.y * s0v);
            __half2 a1 = __floats2half2_rn(c.z * s0v, c.w * s0v);
            __half2 d0 = __floats2half2_rn(c.x * s1v, c.y * s1v);
            __half2 d1 = __floats2half2_rn(c.z * s1v, c.w * s1v);
            uint2 u0 = make_uint2(*(uint32_t*)&a0, *(uint32_t*)&a1);
            uint2 u1 = make_uint2(*(uint32_t*)&d0, *(uint32_t*)&d1);
            *(uint2*)(base0 + (size_t)t * (64 * 136)) = u0;
            *(uint2*)(base1 + (size_t)t * (64 * 136)) = u1;
        }
    } else {
        int gw = (bx - 4096) * 4 + (tid >> 5);
        int lane = tid & 31;
        int b = gw >> 9, oc = gw & 511;
        const float* q = g_q2 + (size_t)oc * CCH;
        const float* s = g_s + b * CCH;
        float a = 0.f;
#pragma unroll 4
        for (int j = lane; j < CCH; j += 32) {
            float sv = s[j];
            a += sv * sv * q[j];
        }
#pragma unroll
        for (int o = 16; o; o >>= 1) a += __shfl_xor_sync(0xFFFFFFFFu, a, o);
        if (lane == 0) g_sigma[b * CCH + oc] = rsqrtf(a + EPSV);
    }
}

// ---------------- mbarrier / bulk-copy / mma helpers ----------------
#define MBAR_INIT(addr, cnt) \
    asm volatile("mbarrier.init.shared.b64 [%0], %1;" :: "r"(addr), "r"(cnt) : "memory")
#define MBAR_EXPECT_TX(addr, bytes) \
    asm volatile("mbarrier.arrive.expect_tx.shared.b64 _, [%0], %1;" :: "r"(addr), "r"(bytes) : "memory")
#define MBAR_ARRIVE(addr) \
    asm volatile("mbarrier.arrive.shared.b64 _, [%0];" :: "r"(addr) : "memory")
#define MBAR_WAIT(addr, ph) do {                                              \
    asm volatile(                                                             \
        "{\n\t.reg .pred P1;\n\t"                                             \
        "WL_%=:\n\t"                                                          \
        "mbarrier.try_wait.parity.acquire.cta.shared::cta.b64 P1, [%0], %1, 0x989680;\n\t" \
        "@P1 bra.uni WD_%=;\n\t"                                              \
        "bra.uni WL_%=;\n\t"                                                  \
        "WD_%=:\n\t}"                                                         \
        :: "r"(addr), "r"(ph) : "memory");                                    \
} while (0)
#define MBAR_WAIT_RLX(addr, ph) do {                                          \
    asm volatile(                                                             \
        "{\n\t.reg .pred P1;\n\t"                                             \
        "WL_%=:\n\t"                                                          \
        "mbarrier.try_wait.parity.relaxed.cta.shared::cta.b64 P1, [%0], %1, 0x989680;\n\t" \
        "@P1 bra.uni WD_%=;\n\t"                                              \
        "bra.uni WL_%=;\n\t"                                                  \
        "WD_%=:\n\t}"                                                         \
        :: "r"(addr), "r"(ph) : "memory");                                    \
} while (0)
#define BULK_G2S(dst, src, bytes, mbar)                                       \
    asm volatile("cp.async.bulk.shared::cluster.global.mbarrier::complete_tx::bytes " \
                 "[%0], [%1], %2, [%3];"                                      \
                 :: "r"(dst), "l"(src), "r"(bytes), "r"(mbar) : "memory")

__device__ __forceinline__ void mma16816(float* c, const uint32_t* a, uint32_t b0, uint32_t b1) {
    asm volatile(
        "mma.sync.aligned.m16n8k16.row.col.f32.f16.f16.f32 "
        "{%0,%1,%2,%3}, {%4,%5,%6,%7}, {%8,%9}, {%0,%1,%2,%3};\n"
        : "+f"(c[0]), "+f"(c[1]), "+f"(c[2]), "+f"(c[3])
        : "r"(a[0]), "r"(a[1]), "r"(a[2]), "r"(a[3]), "r"(b0), "r"(b1));
}
__device__ __forceinline__ void ldsm_x4(uint32_t* r, uint32_t addr) {
    asm volatile("ldmatrix.sync.aligned.m8n8.x4.shared.b16 {%0,%1,%2,%3}, [%4];\n"
                 : "=r"(r[0]), "=r"(r[1]), "=r"(r[2]), "=r"(r[3]) : "r"(addr));
}
__device__ __forceinline__ void ldsm_x4_t(uint32_t* r, uint32_t addr) {
    asm volatile("ldmatrix.sync.aligned.m8n8.x4.trans.shared.b16 {%0,%1,%2,%3}, [%4];\n"
                 : "=r"(r[0]), "=r"(r[1]), "=r"(r[2]), "=r"(r[3]) : "r"(addr));
}

// ---------------- main conv kernel: PERSISTENT, rings continue across tiles ----------------
// grid = #SMs. CTA c handles tiles c, c+nsm, ... Tile: nt=tau&3, mt=(tau>>2)&15, b=tau>>6.
#define XBYTES 57024u
#define BBYTES 17408u
#define BSTG   52224u
#define DATA0  1024u
#define XOFF(i)  (DATA0 + (i) * XBYTES)
#define BOFF(i)  (DATA0 + 2u * XBYTES + (i) * BSTG)
#define SMEM_NEED (1024 + 2 * 57024 + 2 * 52224)   // 219520

__global__ void __launch_bounds__(512, 1)
k_conv(const float* __restrict__ noise, const float* __restrict__ nzw,
       const float* __restrict__ bias, float* __restrict__ out, int nsm) {
    extern __shared__ char smem_raw[];
    const uint32_t sb = ((uint32_t)__cvta_generic_to_shared(smem_raw) + 1023u) & ~1023u;
#define FBF(s) (sb + (uint32_t)(s) * 8u)
#define FBE(s) (sb + 32u + (uint32_t)(s) * 8u)
#define FXF(s) (sb + 64u + (uint32_t)(s) * 8u)
#define FXE(s) (sb + 96u + (uint32_t)(s) * 8u)

    const int c = blockIdx.x;
    const int tid = threadIdx.x, lane = tid & 31, wid = tid >> 5;
    const int warp_m = wid & 3;
    const int warp_n = wid >> 2;
    const int ntc = (NTILES - c + nsm - 1) / nsm;
    if (ntc <= 0) return;
    const int totB = 24 * ntc, totX = 8 * ntc;

    if (tid == 0) {
#pragma unroll
        for (int s = 0; s < 2; s++) {
            MBAR_INIT(FBF(s), 1); MBAR_INIT(FBE(s), 16);
            MBAR_INIT(FXF(s), 1); MBAR_INIT(FXE(s), 16);
        }
    }
    __syncthreads();

    if (tid == 0) {
        int tau0 = c;
        const __half* xs0 = g_xp2 +
            ((size_t)((tau0 >> 6) * 8 + 0) * 66 + ((tau0 >> 2) & 15) * 4) * (66 * 72);
        const __half* bs0 = g_wmodP +
            (size_t)((tau0 >> 6) * 4 + (tau0 & 3)) * 8 * KTAP * 64 * 136;
        MBAR_EXPECT_TX(FXF(0), XBYTES);
        BULK_G2S(sb + XOFF(0), xs0, XBYTES, FXF(0));
#pragma unroll
        for (int j = 0; j < 2; j++) {
            MBAR_EXPECT_TX(FBF(j), BSTG);
            BULK_G2S(sb + BOFF(j), bs0 + (size_t)j * 3 * (64 * 136), BSTG, FBF(j));
        }
    }

    float acc[4][4][4];
#pragma unroll
    for (int i = 0; i < 4; i++)
#pragma unroll
        for (int j = 0; j < 4; j++)
#pragma unroll
            for (int k = 0; k < 4; k++) acc[i][j][k] = 0.f;

    const int off_m = ((lane >> 3) & 1) * 8 + (lane & 7);
    const int off_k2 = ((lane >> 4) * 8) * 2;
    const uint32_t b_lane_off = (uint32_t)((lane & 15) * 272 +
                                           (warp_n * 32 + (lane >> 4) * 8) * 2);
    const int g2 = lane >> 2, tq = lane & 3;

    int gb = 0, gx = 0;
    for (int lt = 0; lt < ntc; lt++) {
        const int tau = c + nsm * lt;
        const int nt = tau & 3, mt = (tau >> 2) & 15, b = tau >> 6;
        const int y0 = mt * 4;

        for (int kc = 0; kc < 8; kc++, gx++) {
            MBAR_WAIT(FXF(gx & 1), (gx >> 1) & 1);
            for (int sidx = 0; sidx < 3; sidx++, gb++) {
                MBAR_WAIT(FBF(gb & 1), (gb >> 1) & 1);

                const uint32_t Arow = sb + XOFF(gx & 1) +
                    (uint32_t)(((warp_m + sidx) * 66 + off_m) * 144) + off_k2;
                const uint32_t Bst = sb + BOFF(gb & 1) + b_lane_off;

#pragma unroll
                for (int tp = 0; tp < 3; tp++) {
                    const uint32_t A0 = Arow + (uint32_t)(tp * 144);
                    const uint32_t Bb = Bst + (uint32_t)tp * BBYTES;
#pragma unroll
                    for (int k16 = 0; k16 < 4; k16++) {
                        uint32_t a[4][4];
#pragma unroll
                        for (int mf = 0; mf < 4; mf++)
                            ldsm_x4(a[mf], A0 + mf * 2304 + k16 * 32);
#pragma unroll
                        for (int g = 0; g < 2; g++) {
                            uint32_t bf[4];
                            ldsm_x4_t(bf, Bb + k16 * (16 * 272) + g * 32);
#pragma unroll
                            for (int mf = 0; mf < 4; mf++) {
                                mma16816(acc[mf][g * 2],     a[mf], bf[0], bf[1]);
                                mma16816(acc[mf][g * 2 + 1], a[mf], bf[2], bf[3]);
                            }
                        }
                    }
                }

                if (lane == 0) {
                    MBAR_ARRIVE(FBE(gb & 1));
                    if (sidx == 2) MBAR_ARRIVE(FXE(gx & 1));
                    if (wid == (gb & 15)) {        // rotating producer duty
                        int j = gb + 2;
                        if (j < totB) {
                            int js = j & 1;
                            MBAR_WAIT_RLX(FBE(js), ((j >> 1) + 1) & 1);
                            int lt2 = j / 24, r2 = j - lt2 * 24;
                            int jkc = r2 / 3, jsx = r2 - jkc * 3;
                            int tau2 = c + nsm * lt2;
                            const __half* bs2 = g_wmodP +
                                (size_t)((tau2 >> 6) * 4 + (tau2 & 3)) * 8 * KTAP * 64 * 136;
                            MBAR_EXPECT_TX(FBF(js), BSTG);
                            BULK_G2S(sb + BOFF(js),
                                     bs2 + (size_t)(jkc * KTAP + jsx * 3) * (64 * 136),
                                     BSTG, FBF(js));
                        }
                        if (sidx == 0) {
                            int jx = gx + 1;
                            if (jx < totX) {
                                int js2 = jx & 1;
                                MBAR_WAIT_RLX(FXE(js2), ((jx >> 1) + 1) & 1);
                                int lt3 = jx >> 3, jxkc = jx & 7;
                                int tau3 = c + nsm * lt3;
                                const __half* xs3 = g_xp2 +
                                    ((size_t)((tau3 >> 6) * 8 + jxkc) * 66 +
                                     ((tau3 >> 2) & 15) * 4) * (66 * 72);
                                MBAR_EXPECT_TX(FXF(js2), XBYTES);
                                BULK_G2S(sb + XOFF(js2), xs3, XBYTES, FXF(js2));
                            }
                        }
                    }
                }
            }
        }

        // -------- per-tile epilogue: sigma post-scale + noise + bias + leaky relu --------
        {
            const int yrow = y0 + warp_m;
            const float* nrow = noise + (size_t)b * NPIX + (size_t)yrow * HW;
            float nzv[4][2];
#pragma unroll
            for (int mf = 0; mf < 4; mf++) {
                nzv[mf][0] = nrow[mf * 16 + g2];
                nzv[mf][1] = nrow[mf * 16 + g2 + 8];
            }
            const size_t outb = (size_t)b * CCH * NPIX;
#pragma unroll
            for (int nf = 0; nf < 4; nf++) {
                int oc = nt * 128 + warp_n * 32 + nf * 8 + tq * 2;
                float sg0 = g_sigma[b * CCH + oc], sg1 = g_sigma[b * CCH + oc + 1];
                float nw0 = nzw[oc], nw1 = nzw[oc + 1];
                float bi0 = bias[oc], bi1 = bias[oc + 1];
                float* o0 = out + outb + (size_t)oc * NPIX + (size_t)yrow * HW;
#pragma unroll
                for (int mf = 0; mf < 4; mf++) {
                    int x0 = mf * 16 + g2;
                    float v;
                    v = acc[mf][nf][0] * sg0 + nw0 * nzv[mf][0] + bi0; __stwt(o0 + x0,            v > 0.f ? v : 0.2f * v);
                    v = acc[mf][nf][1] * sg1 + nw1 * nzv[mf][0] + bi1; __stwt(o0 + NPIX + x0,     v > 0.f ? v : 0.2f * v);
                    v = acc[mf][nf][2] * sg0 + nw0 * nzv[mf][1] + bi0; __stwt(o0 + x0 + 8,        v > 0.f ? v : 0.2f * v);
                    v = acc[mf][nf][3] * sg1 + nw1 * nzv[mf][1] + bi1; __stwt(o0 + NPIX + x0 + 8, v > 0.f ? v : 0.2f * v);
                }
            }
#pragma unroll
            for (int i = 0; i < 4; i++)
#pragma unroll
                for (int j = 0; j < 4; j++)
#pragma unroll
                    for (int k = 0; k < 4; k++) acc[i][j][k] = 0.f;
        }
    }
}

// ---------------- launcher (3 launches; conv persistent, grid = #SMs) ----------------
extern "C" void kernel_launch(void* const* d_in, const int* in_sizes, int n_in,
                              void* d_out, int out_size) {
    const float* x     = (const float*)d_in[0];
    const float* w     = (const float*)d_in[1];
    const float* sw    = (const float*)d_in[2];
    const float* sb    = (const float*)d_in[3];
    const float* cw    = (const float*)d_in[4];
    const float* nzw   = (const float*)d_in[5];
    const float* bias  = (const float*)d_in[6];
    const float* noise = (const float*)d_in[7];
    float* out = (float*)d_out;

    int nsm = 148;
    cudaDeviceGetAttribute(&nsm, cudaDevAttrMultiProcessorCount, 0);
    if (nsm <= 0 || nsm > NTILES) nsm = 148;

    cudaFuncSetAttribute((const void*)k_conv,
                         cudaFuncAttributeMaxDynamicSharedMemorySize, SMEM_NEED);

    k_p1<<<8448 + 256 + 2048, 128>>>(x, cw, w, sw, sb);
    k_p2<<<4096 + 2048, 128>>>();
    k_conv<<<nsm, 512, SMEM_NEED>>>(noise, nzw, bias, out, nsm);
}